// round 8
// baseline (speedup 1.0000x reference)
#include <cuda_runtime.h>
#include <math.h>

// out[b,c,:] = irfft( rfft(x,16384) * Kspec[c], 16384 )[:8192]
// Single fused kernel: bids [0,128) compute Kspec for 2 channels each and
// release flags; bids [128, 128+2048) are conv rows that spin on their
// channel's flag only right before the spectral multiply.
// FFT: fwd radix [8,8,8,8,(2)], inv [(2),8,8,8,8]; r2 seams + spectral
// multiply fused in registers; global I/O fused into first/last stages.
// Twiddles w1..w7 from 7 smem tables (broadcast LDS replaces cmul chains).

#define N_FFT   8192
#define HALF_N  4096
#define NT      1024
#define L_SEQ   8192
#define NCHAN   256
#define NROWS   2048
#define NKB     128

#define BUF_PAD 8704
#define SKEW(a) ((a) + ((a) >> 4))
#define TWT     1024

__device__ float2 g_kspec[(size_t)NCHAN * (N_FFT + 1)];
__device__ int    g_flag[NCHAN];   // static zero-init; stays set after run 1 (benign)

__device__ __forceinline__ float2 cmul(float2 a, float2 b) {
    return make_float2(a.x * b.x - a.y * b.y, a.x * b.y + a.y * b.x);
}
__device__ __forceinline__ float2 cmulc(float2 a, float2 b) {   // a * conj(b)
    return make_float2(a.x * b.x + a.y * b.y, a.y * b.x - a.x * b.y);
}
__device__ __forceinline__ float2 cadd(float2 a, float2 b) { return make_float2(a.x + b.x, a.y + b.y); }
__device__ __forceinline__ float2 csub(float2 a, float2 b) { return make_float2(a.x - b.x, a.y - b.y); }

template <int INV>
__device__ __forceinline__ void dft8(float2* v) {
    const float u = 0.70710678118654752f;
    float2 apc = cadd(v[0], v[4]), amc = csub(v[0], v[4]);
    float2 bpd = cadd(v[2], v[6]), bmd = csub(v[2], v[6]);
    float2 E0 = cadd(apc, bpd), E2 = csub(apc, bpd), E1, E3;
    if (!INV) { E1 = make_float2(amc.x + bmd.y, amc.y - bmd.x); E3 = make_float2(amc.x - bmd.y, amc.y + bmd.x); }
    else      { E1 = make_float2(amc.x - bmd.y, amc.y + bmd.x); E3 = make_float2(amc.x + bmd.y, amc.y - bmd.x); }
    apc = cadd(v[1], v[5]); amc = csub(v[1], v[5]);
    bpd = cadd(v[3], v[7]); bmd = csub(v[3], v[7]);
    float2 O0 = cadd(apc, bpd), O2 = csub(apc, bpd), O1, O3;
    if (!INV) { O1 = make_float2(amc.x + bmd.y, amc.y - bmd.x); O3 = make_float2(amc.x - bmd.y, amc.y + bmd.x); }
    else      { O1 = make_float2(amc.x - bmd.y, amc.y + bmd.x); O3 = make_float2(amc.x + bmd.y, amc.y - bmd.x); }
    float2 T1, T2, T3;
    if (!INV) {
        T1 = make_float2(u * (O1.x + O1.y), u * (O1.y - O1.x));
        T2 = make_float2(O2.y, -O2.x);
        T3 = make_float2(u * (O3.y - O3.x), -u * (O3.x + O3.y));
    } else {
        T1 = make_float2(u * (O1.x - O1.y), u * (O1.x + O1.y));
        T2 = make_float2(-O2.y, O2.x);
        T3 = make_float2(-u * (O3.x + O3.y), u * (O3.x - O3.y));
    }
    v[0] = cadd(E0, O0); v[4] = csub(E0, O0);
    v[1] = cadd(E1, T1); v[5] = csub(E1, T1);
    v[2] = cadd(E2, T2); v[6] = csub(E2, T2);
    v[3] = cadd(E3, T3); v[7] = csub(E3, T3);
}

// forward dft8 with v[4..7] == 0 implied
__device__ __forceinline__ void dft8_half(float2* v) {
    const float u = 0.70710678118654752f;
    float2 E0 = cadd(v[0], v[2]), E2 = csub(v[0], v[2]);
    float2 E1 = make_float2(v[0].x + v[2].y, v[0].y - v[2].x);
    float2 E3 = make_float2(v[0].x - v[2].y, v[0].y + v[2].x);
    float2 O0 = cadd(v[1], v[3]), O2 = csub(v[1], v[3]);
    float2 O1 = make_float2(v[1].x + v[3].y, v[1].y - v[3].x);
    float2 O3 = make_float2(v[1].x - v[3].y, v[1].y + v[3].x);
    float2 T1 = make_float2(u * (O1.x + O1.y), u * (O1.y - O1.x));
    float2 T2 = make_float2(O2.y, -O2.x);
    float2 T3 = make_float2(u * (O3.y - O3.x), -u * (O3.x + O3.y));
    v[0] = cadd(E0, O0); v[4] = csub(E0, O0);
    v[1] = cadd(E1, T1); v[5] = csub(E1, T1);
    v[2] = cadd(E2, T2); v[6] = csub(E2, T2);
    v[3] = cadd(E3, T3); v[7] = csub(E3, T3);
}

// radix-8 Stockham stage with 7 twiddle tables tws[(m-1)*1024 + e] = W^{m e}
template <int INV>
__device__ __forceinline__ void stage_r8(const float2* __restrict__ x, float2* __restrict__ y,
                                         const float2* __restrict__ tws, int s, int tid) {
    const int q = tid & (s - 1);
    const int e = tid - q;
    float2 v[8];
#pragma unroll
    for (int j = 0; j < 8; j++) v[j] = x[SKEW(tid + (j << 10))];
    dft8<INV>(v);
    const int o = q + (e << 3);
    y[SKEW(o)] = v[0];
#pragma unroll
    for (int m = 1; m < 8; m++) {
        float2 w = tws[((m - 1) << 10) + e];
        y[SKEW(o + m * s)] = INV ? cmulc(v[m], w) : cmul(w, v[m]);
    }
}

// stage-1 (s=1) write from registers, e = tid
__device__ __forceinline__ void stage1_write(float2* __restrict__ y, const float2* v,
                                             const float2* __restrict__ tws, int tid) {
    const int o = tid << 3;
    y[SKEW(o)] = v[0];
#pragma unroll
    for (int m = 1; m < 8; m++) {
        float2 w = tws[((m - 1) << 10) + tid];
        y[SKEW(o + m)] = cmul(w, v[m]);
    }
}

// unpack pair: Z[k], Z[8192-k], E=e^{-i pi k/8192} -> X[k], X[8192-k]
__device__ __forceinline__ void unpack_pair(float2 Zk, float2 Zn, float2 E,
                                            float2* Xk, float2* Xn) {
    float2 A = make_float2(0.5f * (Zk.x + Zn.x), 0.5f * (Zk.y - Zn.y));
    float2 D = make_float2(0.5f * (Zk.x - Zn.x), 0.5f * (Zk.y + Zn.y));
    float2 B = make_float2(D.y, -D.x);
    float2 EB = cmul(E, B);
    *Xk = make_float2(A.x + EB.x, A.y + EB.y);
    *Xn = make_float2(A.x - EB.x, -(A.y - EB.y));
}

__device__ __forceinline__ void spec_pair(float2 Zk, float2 Zn, float2 Kk, float2 Kn,
                                          float2 E, float2* Wk, float2* Wn) {
    float2 Xk, Xn;
    unpack_pair(Zk, Zn, E, &Xk, &Xn);
    float2 Yk = cmul(Xk, Kk);
    float2 Yn = cmul(Xn, Kn);
    float2 Ay = make_float2(0.5f * (Yk.x + Yn.x), 0.5f * (Yk.y - Yn.y));
    float2 Dy = make_float2(0.5f * (Yk.x - Yn.x), 0.5f * (Yk.y + Yn.y));
    float2 By = cmulc(Dy, E);
    *Wk = make_float2(Ay.x - By.y,  Ay.y + By.x);
    *Wn = make_float2(Ay.x + By.y, -Ay.y + By.x);
}

__device__ __forceinline__ float smooth_squash(const float* rk, int i) {
    float ssum = 0.f;
#pragma unroll
    for (int d = -3; d <= 3; d++) {
        int j = i + d;
        j = (j < 0) ? -j : j;
        j = (j > L_SEQ - 1) ? (2 * (L_SEQ - 1) - j) : j;
        ssum += rk[j];
    }
    float v = ssum * (1.0f / 7.0f);
    float a = fabsf(v) - 0.003f;
    return (a > 0.f) ? copysignf(a, v) : 0.f;
}

// smem: b0[BUF_PAD] | b1[BUF_PAD] | tws[7*1024] | twh[2052]
#define SMEM_BYTES ((2 * BUF_PAD + 7 * TWT + 2052) * (int)sizeof(float2))

__global__ void __launch_bounds__(NT, 1) fused_kernel(const float* __restrict__ x,
                                                      const float* __restrict__ kern,
                                                      float* __restrict__ out) {
    extern __shared__ float2 sm2[];
    float2* b0  = sm2;
    float2* b1  = sm2 + BUF_PAD;
    float2* tws = sm2 + 2 * BUF_PAD;
    float2* twh = tws + 7 * TWT;

    const int tid = threadIdx.x;

    // fill tables: tws[(m-1)*1024+j] = e^{-2 pi i m j/8192}; twh[k]=e^{-i pi k/8192}
    {
        float s, c;
#pragma unroll
        for (int m = 1; m <= 7; m++) {
            sincospif((float)(m * tid) * (1.0f / 4096.0f), &s, &c);
            tws[((m - 1) << 10) + tid] = make_float2(c, -s);
        }
        for (int k = tid; k <= 2048; k += NT) {
            sincospif((float)k * (1.0f / 8192.0f), &s, &c);
            twh[k] = make_float2(c, -s);
        }
    }
    __syncthreads();

    if (blockIdx.x < NKB) {
        // ---------------- kspec: two channels per CTA ----------------
        for (int cc = 0; cc < 2; cc++) {
            const int c = (blockIdx.x << 1) + cc;
            const float* kr = kern + (size_t)c * L_SEQ;
            float* rk = (float*)b1;
            for (int i = tid; i < L_SEQ; i += NT) rk[i] = kr[i];
            __syncthreads();

            // fused stage 1 from smooth/squash registers
            {
                float2 v[8];
#pragma unroll
                for (int j = 0; j < 4; j++) {
                    const int n = tid + (j << 10);
                    v[j] = make_float2(smooth_squash(rk, 2 * n), smooth_squash(rk, 2 * n + 1));
                }
                dft8_half(v);
                stage1_write(b0, v, tws, tid);
            }
            __syncthreads();
            stage_r8<0>(b0, b1, tws, 8, tid);   __syncthreads();
            stage_r8<0>(b1, b0, tws, 64, tid);  __syncthreads();
            stage_r8<0>(b0, b1, tws, 512, tid); __syncthreads();
            // P = b1; fused r2 finisher + unpack + store (scaled 1/N)
            float2* Kc = g_kspec + (size_t)c * (N_FFT + 1);
            const float inv = 1.0f / (float)N_FFT;
#pragma unroll 1
            for (int u = 0; u < 2; u++) {
                const int q = tid + (u << 10);
                if (q == 0) {
                    float2 Pa = b1[SKEW(0)],    Pb = b1[SKEW(4096)];
                    float2 Pc = b1[SKEW(2048)], Pd = b1[SKEW(6144)];
                    float2 Z0 = cadd(Pa, Pb), Z4 = csub(Pa, Pb);
                    float2 Z2 = cadd(Pc, Pd), Z6 = csub(Pc, Pd);
                    Kc[0]     = make_float2((Z0.x + Z0.y) * inv, 0.f);
                    Kc[N_FFT] = make_float2((Z0.x - Z0.y) * inv, 0.f);
                    Kc[4096]  = make_float2(Z4.x * inv, -Z4.y * inv);
                    float2 X2, X6;
                    unpack_pair(Z2, Z6, twh[2048], &X2, &X6);
                    Kc[2048] = make_float2(X2.x * inv, X2.y * inv);
                    Kc[6144] = make_float2(X6.x * inv, X6.y * inv);
                } else {
                    const int r = 4096 - q;
                    float2 Pa = b1[SKEW(q)], Pb = b1[SKEW(q + 4096)];
                    float2 Pc = b1[SKEW(r)], Pd = b1[SKEW(r + 4096)];
                    float2 Zq = cadd(Pa, Pb), Zq4 = csub(Pa, Pb);
                    float2 Zr = cadd(Pc, Pd), Znq = csub(Pc, Pd);
                    float2 Eq = twh[q];
                    float2 Er = make_float2(-Eq.y, -Eq.x);        // E(4096-q)
                    float2 Xq, Xnq, Xr, Xpq;
                    unpack_pair(Zq, Znq, Eq, &Xq, &Xnq);
                    unpack_pair(Zr, Zq4, Er, &Xr, &Xpq);
                    Kc[q]         = make_float2(Xq.x * inv,  Xq.y * inv);
                    Kc[N_FFT - q] = make_float2(Xnq.x * inv, Xnq.y * inv);
                    Kc[r]         = make_float2(Xr.x * inv,  Xr.y * inv);
                    Kc[4096 + q]  = make_float2(Xpq.x * inv, Xpq.y * inv);
                }
            }
            // release: all stores visible, then set flag
            __threadfence();
            __syncthreads();
            if (tid == 0) *((volatile int*)&g_flag[c]) = 1;
            __syncthreads();
        }
        return;
    }

    // ---------------- conv: one CTA per (b,c) row ----------------
    const int row = blockIdx.x - NKB;
    const int c   = row & (NCHAN - 1);
    const float2* xr = (const float2*)(x + (size_t)row * L_SEQ);

    // fwd stage 1: global read fused (upper half zero)
    {
        float2 v[8];
#pragma unroll
        for (int j = 0; j < 4; j++) v[j] = xr[tid + (j << 10)];
        dft8_half(v);
        stage1_write(b0, v, tws, tid);
    }
    __syncthreads();
    stage_r8<0>(b0, b1, tws, 8, tid);   __syncthreads();
    stage_r8<0>(b1, b0, tws, 64, tid);  __syncthreads();
    stage_r8<0>(b0, b1, tws, 512, tid); __syncthreads();
    // P = b1

    // acquire the channel spectrum (overlaps with kspec in wave 1)
    if (tid == 0) {
        while (*((volatile int*)&g_flag[c]) == 0) { }
    }
    __syncthreads();
    __threadfence();

    // fused: fwd r2 finisher + spectral multiply + inv r2 opener -> b0
    const float2* Kc = g_kspec + (size_t)c * (N_FFT + 1);
#pragma unroll 1
    for (int u = 0; u < 2; u++) {
        const int q = tid + (u << 10);
        if (q == 0) {
            float2 Pa = b1[SKEW(0)],    Pb = b1[SKEW(4096)];
            float2 Pc = b1[SKEW(2048)], Pd = b1[SKEW(6144)];
            float2 Z0 = cadd(Pa, Pb), Z4 = csub(Pa, Pb);
            float2 Z2 = cadd(Pc, Pd), Z6 = csub(Pc, Pd);
            float X0 = Z0.x + Z0.y, XN = Z0.x - Z0.y;
            float2 K0 = Kc[0], KN = Kc[N_FFT];
            float2 Y0 = make_float2(X0 * K0.x, X0 * K0.y);
            float2 YN = make_float2(XN * KN.x, XN * KN.y);
            float2 Ay = make_float2(0.5f * (Y0.x + YN.x), 0.5f * (Y0.y - YN.y));
            float2 Dy = make_float2(0.5f * (Y0.x - YN.x), 0.5f * (Y0.y + YN.y));
            float2 W0 = make_float2(Ay.x - Dy.y, Ay.y + Dy.x);
            float2 W4, Wd;
            spec_pair(Z4, Z4, Kc[4096], Kc[4096], make_float2(0.f, -1.f), &W4, &Wd);
            float2 W2, W6;
            spec_pair(Z2, Z6, Kc[2048], Kc[6144], twh[2048], &W2, &W6);
            b0[SKEW(0)] = cadd(W0, W4);
            b0[SKEW(1)] = csub(W0, W4);
            b0[SKEW(4096)] = cadd(W2, W6);
            float2 t = csub(W2, W6);                 // * winv(2048) = i
            b0[SKEW(4097)] = make_float2(-t.y, t.x);
        } else {
            const int r = 4096 - q;
            float2 Pa = b1[SKEW(q)], Pb = b1[SKEW(q + 4096)];
            float2 Pc = b1[SKEW(r)], Pd = b1[SKEW(r + 4096)];
            float2 Zq = cadd(Pa, Pb), Zq4 = csub(Pa, Pb);
            float2 Zr = cadd(Pc, Pd), Znq = csub(Pc, Pd);
            float2 Eq = twh[q];
            float2 Er = make_float2(-Eq.y, -Eq.x);
            float2 Wq, Wnq, Wr, Wpq;
            spec_pair(Zq, Znq, Kc[q], Kc[N_FFT - q], Eq, &Wq, &Wnq);
            spec_pair(Zr, Zq4, Kc[r], Kc[4096 + q], Er, &Wr, &Wpq);
            float2 wq = cmul(Eq, Eq);                 // twiddle^q (fwd sense)
            float2 wr = make_float2(-wq.x, wq.y);     // Er^2 = -conj(Eq^2)
            b0[SKEW(2 * q)]     = cadd(Wq, Wpq);
            b0[SKEW(2 * q + 1)] = cmulc(csub(Wq, Wpq), wq);
            b0[SKEW(2 * r)]     = cadd(Wr, Wnq);
            b0[SKEW(2 * r + 1)] = cmulc(csub(Wr, Wnq), wr);
        }
    }
    __syncthreads();

    stage_r8<1>(b0, b1, tws, 2, tid);   __syncthreads();
    stage_r8<1>(b1, b0, tws, 16, tid);  __syncthreads();
    stage_r8<1>(b0, b1, tws, 128, tid); __syncthreads();

    // final inverse stage s=1024 (twiddle-free): store first half to global
    {
        float2 v[8];
#pragma unroll
        for (int j = 0; j < 8; j++) v[j] = b1[SKEW(tid + (j << 10))];
        dft8<1>(v);
        float2* outr = (float2*)(out + (size_t)row * L_SEQ);
#pragma unroll
        for (int j = 0; j < 4; j++) outr[tid + (j << 10)] = v[j];
    }
}

// ---------------------------------------------------------------------------
extern "C" void kernel_launch(void* const* d_in, const int* in_sizes, int n_in,
                              void* d_out, int out_size) {
    const float* x;
    const float* kern;
    if (in_sizes[0] == NROWS * L_SEQ) {
        x    = (const float*)d_in[0];
        kern = (const float*)d_in[1];
    } else {
        x    = (const float*)d_in[1];
        kern = (const float*)d_in[0];
    }
    float* out = (float*)d_out;

    cudaFuncSetAttribute(fused_kernel, cudaFuncAttributeMaxDynamicSharedMemorySize, SMEM_BYTES);
    fused_kernel<<<NKB + NROWS, NT, SMEM_BYTES>>>(x, kern, out);
}

// round 9
// speedup vs baseline: 1.0986x; 1.0986x over previous
#include <cuda_runtime.h>
#include <math.h>

// out[b,c,:] = irfft( rfft(x,16384) * Kspec[c], 16384 )[:8192]
// Two kernels: kspec (256 CTAs) then conv (2048 CTAs).
// FFT: fwd radix [8,8,8,8,(2)], inv [(2),8,8,8,8]; r2 seams + spectral multiply
// fused in registers; global I/O fused into first/last stages.
// Twiddles w1..w7 from 7 smem tables (broadcast LDS replaces cmul chains).

#define N_FFT   8192
#define HALF_N  4096
#define NT      1024
#define L_SEQ   8192
#define NCHAN   256
#define NROWS   2048

#define BUF_PAD 8704
#define SKEW(a) ((a) + ((a) >> 4))
#define TWT     1024

__device__ float2 g_kspec[(size_t)NCHAN * (N_FFT + 1)];

__device__ __forceinline__ float2 cmul(float2 a, float2 b) {
    return make_float2(a.x * b.x - a.y * b.y, a.x * b.y + a.y * b.x);
}
__device__ __forceinline__ float2 cmulc(float2 a, float2 b) {   // a * conj(b)
    return make_float2(a.x * b.x + a.y * b.y, a.y * b.x - a.x * b.y);
}
__device__ __forceinline__ float2 cadd(float2 a, float2 b) { return make_float2(a.x + b.x, a.y + b.y); }
__device__ __forceinline__ float2 csub(float2 a, float2 b) { return make_float2(a.x - b.x, a.y - b.y); }

template <int INV>
__device__ __forceinline__ void dft8(float2* v) {
    const float u = 0.70710678118654752f;
    float2 apc = cadd(v[0], v[4]), amc = csub(v[0], v[4]);
    float2 bpd = cadd(v[2], v[6]), bmd = csub(v[2], v[6]);
    float2 E0 = cadd(apc, bpd), E2 = csub(apc, bpd), E1, E3;
    if (!INV) { E1 = make_float2(amc.x + bmd.y, amc.y - bmd.x); E3 = make_float2(amc.x - bmd.y, amc.y + bmd.x); }
    else      { E1 = make_float2(amc.x - bmd.y, amc.y + bmd.x); E3 = make_float2(amc.x + bmd.y, amc.y - bmd.x); }
    apc = cadd(v[1], v[5]); amc = csub(v[1], v[5]);
    bpd = cadd(v[3], v[7]); bmd = csub(v[3], v[7]);
    float2 O0 = cadd(apc, bpd), O2 = csub(apc, bpd), O1, O3;
    if (!INV) { O1 = make_float2(amc.x + bmd.y, amc.y - bmd.x); O3 = make_float2(amc.x - bmd.y, amc.y + bmd.x); }
    else      { O1 = make_float2(amc.x - bmd.y, amc.y + bmd.x); O3 = make_float2(amc.x + bmd.y, amc.y - bmd.x); }
    float2 T1, T2, T3;
    if (!INV) {
        T1 = make_float2(u * (O1.x + O1.y), u * (O1.y - O1.x));
        T2 = make_float2(O2.y, -O2.x);
        T3 = make_float2(u * (O3.y - O3.x), -u * (O3.x + O3.y));
    } else {
        T1 = make_float2(u * (O1.x - O1.y), u * (O1.x + O1.y));
        T2 = make_float2(-O2.y, O2.x);
        T3 = make_float2(-u * (O3.x + O3.y), u * (O3.x - O3.y));
    }
    v[0] = cadd(E0, O0); v[4] = csub(E0, O0);
    v[1] = cadd(E1, T1); v[5] = csub(E1, T1);
    v[2] = cadd(E2, T2); v[6] = csub(E2, T2);
    v[3] = cadd(E3, T3); v[7] = csub(E3, T3);
}

// forward dft8 with v[4..7] == 0 implied
__device__ __forceinline__ void dft8_half(float2* v) {
    const float u = 0.70710678118654752f;
    float2 E0 = cadd(v[0], v[2]), E2 = csub(v[0], v[2]);
    float2 E1 = make_float2(v[0].x + v[2].y, v[0].y - v[2].x);
    float2 E3 = make_float2(v[0].x - v[2].y, v[0].y + v[2].x);
    float2 O0 = cadd(v[1], v[3]), O2 = csub(v[1], v[3]);
    float2 O1 = make_float2(v[1].x + v[3].y, v[1].y - v[3].x);
    float2 O3 = make_float2(v[1].x - v[3].y, v[1].y + v[3].x);
    float2 T1 = make_float2(u * (O1.x + O1.y), u * (O1.y - O1.x));
    float2 T2 = make_float2(O2.y, -O2.x);
    float2 T3 = make_float2(u * (O3.y - O3.x), -u * (O3.x + O3.y));
    v[0] = cadd(E0, O0); v[4] = csub(E0, O0);
    v[1] = cadd(E1, T1); v[5] = csub(E1, T1);
    v[2] = cadd(E2, T2); v[6] = csub(E2, T2);
    v[3] = cadd(E3, T3); v[7] = csub(E3, T3);
}

// radix-8 Stockham stage with 7 twiddle tables tws[(m-1)*1024 + e] = W^{m e}
template <int INV>
__device__ __forceinline__ void stage_r8(const float2* __restrict__ x, float2* __restrict__ y,
                                         const float2* __restrict__ tws, int s, int tid) {
    const int q = tid & (s - 1);
    const int e = tid - q;
    float2 v[8];
#pragma unroll
    for (int j = 0; j < 8; j++) v[j] = x[SKEW(tid + (j << 10))];
    dft8<INV>(v);
    const int o = q + (e << 3);
    y[SKEW(o)] = v[0];
#pragma unroll
    for (int m = 1; m < 8; m++) {
        float2 w = tws[((m - 1) << 10) + e];
        y[SKEW(o + m * s)] = INV ? cmulc(v[m], w) : cmul(w, v[m]);
    }
}

// stage-1 (s=1) write from registers, e = tid
__device__ __forceinline__ void stage1_write(float2* __restrict__ y, const float2* v,
                                             const float2* __restrict__ tws, int tid) {
    const int o = tid << 3;
    y[SKEW(o)] = v[0];
#pragma unroll
    for (int m = 1; m < 8; m++) {
        float2 w = tws[((m - 1) << 10) + tid];
        y[SKEW(o + m)] = cmul(w, v[m]);
    }
}

// fill tables: tws[(m-1)*1024+j] = e^{-2 pi i m j/8192}; twh[k]=e^{-i pi k/8192}, k<=2048
__device__ __forceinline__ void fill_tw(float2* tws, float2* twh, int tid) {
    float s, c;
#pragma unroll
    for (int m = 1; m <= 7; m++) {
        sincospif((float)(m * tid) * (1.0f / 4096.0f), &s, &c);
        tws[((m - 1) << 10) + tid] = make_float2(c, -s);
    }
#pragma unroll
    for (int k = tid; k <= 2048; k += NT) {
        sincospif((float)k * (1.0f / 8192.0f), &s, &c);
        twh[k] = make_float2(c, -s);
    }
}

// unpack pair: Z[k], Z[8192-k], E=e^{-i pi k/8192} -> X[k], X[8192-k]
__device__ __forceinline__ void unpack_pair(float2 Zk, float2 Zn, float2 E,
                                            float2* Xk, float2* Xn) {
    float2 A = make_float2(0.5f * (Zk.x + Zn.x), 0.5f * (Zk.y - Zn.y));
    float2 D = make_float2(0.5f * (Zk.x - Zn.x), 0.5f * (Zk.y + Zn.y));
    float2 B = make_float2(D.y, -D.x);
    float2 EB = cmul(E, B);
    *Xk = make_float2(A.x + EB.x, A.y + EB.y);
    *Xn = make_float2(A.x - EB.x, -(A.y - EB.y));
}

__device__ __forceinline__ void spec_pair(float2 Zk, float2 Zn, float2 Kk, float2 Kn,
                                          float2 E, float2* Wk, float2* Wn) {
    float2 Xk, Xn;
    unpack_pair(Zk, Zn, E, &Xk, &Xn);
    float2 Yk = cmul(Xk, Kk);
    float2 Yn = cmul(Xn, Kn);
    float2 Ay = make_float2(0.5f * (Yk.x + Yn.x), 0.5f * (Yk.y - Yn.y));
    float2 Dy = make_float2(0.5f * (Yk.x - Yn.x), 0.5f * (Yk.y + Yn.y));
    float2 By = cmulc(Dy, E);
    *Wk = make_float2(Ay.x - By.y,  Ay.y + By.x);
    *Wn = make_float2(Ay.x + By.y, -Ay.y + By.x);
}

__device__ __forceinline__ float smooth_squash(const float* rk, int i) {
    float ssum = 0.f;
#pragma unroll
    for (int d = -3; d <= 3; d++) {
        int j = i + d;
        j = (j < 0) ? -j : j;
        j = (j > L_SEQ - 1) ? (2 * (L_SEQ - 1) - j) : j;
        ssum += rk[j];
    }
    float v = ssum * (1.0f / 7.0f);
    float a = fabsf(v) - 0.003f;
    return (a > 0.f) ? copysignf(a, v) : 0.f;
}

// smem: b0[BUF_PAD] | b1[BUF_PAD] | tws[7*1024] | twh[2052]
#define SMEM_BYTES ((2 * BUF_PAD + 7 * TWT + 2052) * (int)sizeof(float2))

// ---------------------------------------------------------------------------
__global__ void __launch_bounds__(NT, 1) kspec_kernel(const float* __restrict__ kern) {
    extern __shared__ float2 sm2[];
    float2* b0  = sm2;
    float2* b1  = sm2 + BUF_PAD;
    float2* tws = sm2 + 2 * BUF_PAD;
    float2* twh = tws + 7 * TWT;
    float*  rk  = (float*)b1;

    const int c   = blockIdx.x;
    const int tid = threadIdx.x;
    const float* kr = kern + (size_t)c * L_SEQ;

    for (int i = tid; i < L_SEQ; i += NT) rk[i] = kr[i];
    fill_tw(tws, twh, tid);
    __syncthreads();

    // fused stage 1 from smooth/squash registers
    {
        float2 v[8];
#pragma unroll
        for (int j = 0; j < 4; j++) {
            const int n = tid + (j << 10);
            v[j] = make_float2(smooth_squash(rk, 2 * n), smooth_squash(rk, 2 * n + 1));
        }
        dft8_half(v);
        stage1_write(b0, v, tws, tid);
    }
    __syncthreads();
    stage_r8<0>(b0, b1, tws, 8, tid);   __syncthreads();
    stage_r8<0>(b1, b0, tws, 64, tid);  __syncthreads();
    stage_r8<0>(b0, b1, tws, 512, tid); __syncthreads();
    // P = b1; fused r2 finisher + unpack + store (scaled 1/N)
    float2* Kc = g_kspec + (size_t)c * (N_FFT + 1);
    const float inv = 1.0f / (float)N_FFT;
#pragma unroll 1
    for (int u = 0; u < 2; u++) {
        const int q = tid + (u << 10);
        if (q == 0) {
            float2 Pa = b1[SKEW(0)],    Pb = b1[SKEW(4096)];
            float2 Pc = b1[SKEW(2048)], Pd = b1[SKEW(6144)];
            float2 Z0 = cadd(Pa, Pb), Z4 = csub(Pa, Pb);
            float2 Z2 = cadd(Pc, Pd), Z6 = csub(Pc, Pd);
            Kc[0]     = make_float2((Z0.x + Z0.y) * inv, 0.f);
            Kc[N_FFT] = make_float2((Z0.x - Z0.y) * inv, 0.f);
            Kc[4096]  = make_float2(Z4.x * inv, -Z4.y * inv);
            float2 X2, X6;
            unpack_pair(Z2, Z6, twh[2048], &X2, &X6);
            Kc[2048] = make_float2(X2.x * inv, X2.y * inv);
            Kc[6144] = make_float2(X6.x * inv, X6.y * inv);
        } else {
            const int r = 4096 - q;
            float2 Pa = b1[SKEW(q)], Pb = b1[SKEW(q + 4096)];
            float2 Pc = b1[SKEW(r)], Pd = b1[SKEW(r + 4096)];
            float2 Zq = cadd(Pa, Pb), Zq4 = csub(Pa, Pb);
            float2 Zr = cadd(Pc, Pd), Znq = csub(Pc, Pd);
            float2 Eq = twh[q];
            float2 Er = make_float2(-Eq.y, -Eq.x);        // E(4096-q)
            float2 Xq, Xnq, Xr, Xpq;
            unpack_pair(Zq, Znq, Eq, &Xq, &Xnq);
            unpack_pair(Zr, Zq4, Er, &Xr, &Xpq);
            Kc[q]         = make_float2(Xq.x * inv,  Xq.y * inv);
            Kc[N_FFT - q] = make_float2(Xnq.x * inv, Xnq.y * inv);
            Kc[r]         = make_float2(Xr.x * inv,  Xr.y * inv);
            Kc[4096 + q]  = make_float2(Xpq.x * inv, Xpq.y * inv);
        }
    }
}

// ---------------------------------------------------------------------------
__global__ void __launch_bounds__(NT, 1) conv_kernel(const float* __restrict__ x,
                                                     float* __restrict__ out) {
    extern __shared__ float2 sm2[];
    float2* b0  = sm2;
    float2* b1  = sm2 + BUF_PAD;
    float2* tws = sm2 + 2 * BUF_PAD;
    float2* twh = tws + 7 * TWT;

    const int row = blockIdx.x;
    const int c   = row & (NCHAN - 1);
    const int tid = threadIdx.x;
    const float2* xr = (const float2*)(x + (size_t)row * L_SEQ);

    fill_tw(tws, twh, tid);
    __syncthreads();

    // fwd stage 1: global read fused (upper half zero)
    {
        float2 v[8];
#pragma unroll
        for (int j = 0; j < 4; j++) v[j] = xr[tid + (j << 10)];
        dft8_half(v);
        stage1_write(b0, v, tws, tid);
    }
    __syncthreads();
    stage_r8<0>(b0, b1, tws, 8, tid);   __syncthreads();
    stage_r8<0>(b1, b0, tws, 64, tid);  __syncthreads();
    stage_r8<0>(b0, b1, tws, 512, tid); __syncthreads();
    // P = b1

    // fused: fwd r2 finisher + spectral multiply + inv r2 opener -> b0
    const float2* Kc = g_kspec + (size_t)c * (N_FFT + 1);
#pragma unroll 1
    for (int u = 0; u < 2; u++) {
        const int q = tid + (u << 10);
        if (q == 0) {
            float2 Pa = b1[SKEW(0)],    Pb = b1[SKEW(4096)];
            float2 Pc = b1[SKEW(2048)], Pd = b1[SKEW(6144)];
            float2 Z0 = cadd(Pa, Pb), Z4 = csub(Pa, Pb);
            float2 Z2 = cadd(Pc, Pd), Z6 = csub(Pc, Pd);
            float X0 = Z0.x + Z0.y, XN = Z0.x - Z0.y;
            float2 K0 = Kc[0], KN = Kc[N_FFT];
            float2 Y0 = make_float2(X0 * K0.x, X0 * K0.y);
            float2 YN = make_float2(XN * KN.x, XN * KN.y);
            float2 Ay = make_float2(0.5f * (Y0.x + YN.x), 0.5f * (Y0.y - YN.y));
            float2 Dy = make_float2(0.5f * (Y0.x - YN.x), 0.5f * (Y0.y + YN.y));
            float2 W0 = make_float2(Ay.x - Dy.y, Ay.y + Dy.x);
            float2 W4, Wd;
            spec_pair(Z4, Z4, Kc[4096], Kc[4096], make_float2(0.f, -1.f), &W4, &Wd);
            float2 W2, W6;
            spec_pair(Z2, Z6, Kc[2048], Kc[6144], twh[2048], &W2, &W6);
            b0[SKEW(0)] = cadd(W0, W4);
            b0[SKEW(1)] = csub(W0, W4);
            b0[SKEW(4096)] = cadd(W2, W6);
            float2 t = csub(W2, W6);                 // * winv(2048) = i
            b0[SKEW(4097)] = make_float2(-t.y, t.x);
        } else {
            const int r = 4096 - q;
            float2 Pa = b1[SKEW(q)], Pb = b1[SKEW(q + 4096)];
            float2 Pc = b1[SKEW(r)], Pd = b1[SKEW(r + 4096)];
            float2 Zq = cadd(Pa, Pb), Zq4 = csub(Pa, Pb);
            float2 Zr = cadd(Pc, Pd), Znq = csub(Pc, Pd);
            float2 Eq = twh[q];
            float2 Er = make_float2(-Eq.y, -Eq.x);
            float2 Wq, Wnq, Wr, Wpq;
            spec_pair(Zq, Znq, Kc[q], Kc[N_FFT - q], Eq, &Wq, &Wnq);
            spec_pair(Zr, Zq4, Kc[r], Kc[4096 + q], Er, &Wr, &Wpq);
            float2 wq = cmul(Eq, Eq);                 // W^q
            float2 wr = make_float2(-wq.x, wq.y);     // Er^2 = -conj(Eq^2)
            b0[SKEW(2 * q)]     = cadd(Wq, Wpq);
            b0[SKEW(2 * q + 1)] = cmulc(csub(Wq, Wpq), wq);
            b0[SKEW(2 * r)]     = cadd(Wr, Wnq);
            b0[SKEW(2 * r + 1)] = cmulc(csub(Wr, Wnq), wr);
        }
    }
    __syncthreads();

    stage_r8<1>(b0, b1, tws, 2, tid);   __syncthreads();
    stage_r8<1>(b1, b0, tws, 16, tid);  __syncthreads();
    stage_r8<1>(b0, b1, tws, 128, tid); __syncthreads();

    // final inverse stage s=1024 (twiddle-free): store first half to global
    {
        float2 v[8];
#pragma unroll
        for (int j = 0; j < 8; j++) v[j] = b1[SKEW(tid + (j << 10))];
        dft8<1>(v);
        float2* outr = (float2*)(out + (size_t)row * L_SEQ);
#pragma unroll
        for (int j = 0; j < 4; j++) outr[tid + (j << 10)] = v[j];
    }
}

// ---------------------------------------------------------------------------
extern "C" void kernel_launch(void* const* d_in, const int* in_sizes, int n_in,
                              void* d_out, int out_size) {
    const float* x;
    const float* kern;
    if (in_sizes[0] == NROWS * L_SEQ) {
        x    = (const float*)d_in[0];
        kern = (const float*)d_in[1];
    } else {
        x    = (const float*)d_in[1];
        kern = (const float*)d_in[0];
    }
    float* out = (float*)d_out;

    cudaFuncSetAttribute(kspec_kernel, cudaFuncAttributeMaxDynamicSharedMemorySize, SMEM_BYTES);
    cudaFuncSetAttribute(conv_kernel,  cudaFuncAttributeMaxDynamicSharedMemorySize, SMEM_BYTES);

    kspec_kernel<<<NCHAN, NT, SMEM_BYTES>>>(kern);
    conv_kernel<<<NROWS, NT, SMEM_BYTES>>>(x, out);
}